// round 14
// baseline (speedup 1.0000x reference)
#include <cuda_runtime.h>
#include <cstddef>
#include <cstdint>

#define NEG_SLOPE 0.2f

static const int N_MAX = 50048;
static const int E_MAX = 1600000;
static const int NB_MAX = 64;

__device__ float g_feat[N_MAX * 128];
__device__ float g_x1[N_MAX * 128];
__device__ float g_x2[N_MAX * 128];
__device__ float g_el[N_MAX * 4];
__device__ float g_er[N_MAX * 4];
__device__ int   g_cnt[N_MAX];
__device__ int   g_off[N_MAX + 1];
__device__ int   g_cur[N_MAX];
__device__ int   g_blk[NB_MAX];
__device__ int   g_blkoff[NB_MAX];
__device__ int   g_csr_src[E_MAX];

// ---------------- CSR build ----------------
__global__ void k_zero_cnt(int n) {
    int i = blockIdx.x * blockDim.x + threadIdx.x;
    if (i < n) g_cnt[i] = 0;
}

__global__ void k_count(const int* __restrict__ dst, int E) {
    int base = (blockIdx.x * blockDim.x + threadIdx.x) * 4;
    if (base + 3 < E) {
        int4 d = *(const int4*)(dst + base);
        atomicAdd(&g_cnt[d.x], 1);
        atomicAdd(&g_cnt[d.y], 1);
        atomicAdd(&g_cnt[d.z], 1);
        atomicAdd(&g_cnt[d.w], 1);
    } else {
        for (int e = base; e < E; e++) atomicAdd(&g_cnt[dst[e]], 1);
    }
}

__global__ void k_scan1(int n) {
    __shared__ int sh[1024];
    int tid = threadIdx.x;
    int i = blockIdx.x * 1024 + tid;
    int v = (i < n) ? g_cnt[i] : 0;
    sh[tid] = v;
    __syncthreads();
#pragma unroll
    for (int o = 1; o < 1024; o <<= 1) {
        int t = (tid >= o) ? sh[tid - o] : 0;
        __syncthreads();
        sh[tid] += t;
        __syncthreads();
    }
    if (i <= n) g_off[i] = sh[tid] - v;
    if (tid == 1023) g_blk[blockIdx.x] = sh[1023];
}

__global__ void k_scan2(int nb) {
    int lane = threadIdx.x;
    int v0 = (lane < nb) ? g_blk[lane] : 0;
    int v1 = (lane + 32 < nb) ? g_blk[lane + 32] : 0;
    int s0 = v0, s1 = v1;
#pragma unroll
    for (int o = 1; o < 32; o <<= 1) {
        int t0 = __shfl_up_sync(0xffffffffu, s0, o);
        int t1 = __shfl_up_sync(0xffffffffu, s1, o);
        if (lane >= o) { s0 += t0; s1 += t1; }
    }
    int tot0 = __shfl_sync(0xffffffffu, s0, 31);
    if (lane < nb) g_blkoff[lane] = s0 - v0;
    if (lane + 32 < nb) g_blkoff[lane + 32] = tot0 + s1 - v1;
}

__global__ void k_scan3(int n, int E) {
    int i = blockIdx.x * blockDim.x + threadIdx.x;
    if (i < n) {
        int o = g_off[i] + g_blkoff[i >> 10];
        g_off[i] = o;
        g_cur[i] = o;
    }
    if (i == 0) g_off[n] = E;
}

__global__ void k_scatter(const int* __restrict__ src, const int* __restrict__ dst, int E) {
    int base = (blockIdx.x * blockDim.x + threadIdx.x) * 4;
    if (base + 3 < E) {
        int4 d = *(const int4*)(dst + base);
        int4 s = *(const int4*)(src + base);
        int p0 = atomicAdd(&g_cur[d.x], 1);
        int p1 = atomicAdd(&g_cur[d.y], 1);
        int p2 = atomicAdd(&g_cur[d.z], 1);
        int p3 = atomicAdd(&g_cur[d.w], 1);
        g_csr_src[p0] = s.x;
        g_csr_src[p1] = s.y;
        g_csr_src[p2] = s.z;
        g_csr_src[p3] = s.w;
    } else {
        for (int e = base; e < E; e++) {
            int p = atomicAdd(&g_cur[dst[e]], 1);
            g_csr_src[p] = src[e];
        }
    }
}

// ---------------- bf16 split helpers ----------------
__device__ __forceinline__ void split_pair(float x0, float x1, uint32_t& hi, uint32_t& lo) {
    uint32_t u0 = __float_as_uint(x0), u1 = __float_as_uint(x1);
    hi = __byte_perm(u0, u1, 0x7632);
    float l0 = x0 - __uint_as_float(u0 & 0xFFFF0000u);
    float l1 = x1 - __uint_as_float(u1 & 0xFFFF0000u);
    asm("cvt.rn.bf16x2.f32 %0, %1, %2;" : "=r"(lo) : "f"(l1), "f"(l0));
}

__device__ __forceinline__ void mma_bf16(float* d, const uint32_t* a, const uint32_t* b) {
    asm volatile(
        "mma.sync.aligned.m16n8k16.row.col.f32.bf16.bf16.f32 "
        "{%0,%1,%2,%3}, {%4,%5,%6,%7}, {%8,%9}, {%0,%1,%2,%3};"
        : "+f"(d[0]), "+f"(d[1]), "+f"(d[2]), "+f"(d[3])
        : "r"(a[0]), "r"(a[1]), "r"(a[2]), "r"(a[3]), "r"(b[0]), "r"(b[1]));
}

// ---------------- GEMM (M=128): bf16 TC, 2-term split, double-buffered ----------------
#define XP 9
template <int K>
__global__ __launch_bounds__(512) void k_gemm_tc(const float* __restrict__ X,
                                                 const float* __restrict__ W,
                                                 float* __restrict__ Y, int n) {
    __shared__ uint32_t Xh[2][128 * XP], Xl[2][128 * XP];
    __shared__ uint32_t Wh[2][128 * XP], Wl[2][128 * XP];
    int tid = threadIdx.x;
    int w = tid >> 5;
    int lane = tid & 31;
    int g = lane >> 2;
    int t = lane & 3;
    int wr = w & 3;
    int wc = w >> 2;
    int r0 = blockIdx.x * 128;

    float acc[2][4][4];
#pragma unroll
    for (int mt = 0; mt < 2; mt++)
#pragma unroll
        for (int nt = 0; nt < 4; nt++)
#pragma unroll
            for (int q = 0; q < 4; q++) acc[mt][nt][q] = 0.f;

    int xrow = tid >> 2;
    int xkq = tid & 3;
    bool xok = (r0 + xrow) < n;
    int wcol = tid & 127;
    int wkh = tid >> 7;

    const int NC = K / 16;

    float4 xv = make_float4(0.f, 0.f, 0.f, 0.f);
    if (xok) xv = ((const float4*)X)[(size_t)(r0 + xrow) * (K / 4) + xkq];
    float wv[2][2];
#pragma unroll
    for (int q = 0; q < 2; q++) {
        int k = 2 * (wkh + 4 * q);
        wv[q][0] = W[(size_t)k * 128 + wcol];
        wv[q][1] = W[(size_t)(k + 1) * 128 + wcol];
    }
    {
        uint32_t h0, l0, h1, l1;
        split_pair(xv.x, xv.y, h0, l0);
        split_pair(xv.z, xv.w, h1, l1);
        int base = xrow * XP + xkq * 2;
        Xh[0][base] = h0; Xl[0][base] = l0;
        Xh[0][base + 1] = h1; Xl[0][base + 1] = l1;
#pragma unroll
        for (int q = 0; q < 2; q++) {
            uint32_t h, l;
            split_pair(wv[q][0], wv[q][1], h, l);
            int kp = wkh + 4 * q;
            Wh[0][wcol * XP + kp] = h;
            Wl[0][wcol * XP + kp] = l;
        }
    }
    __syncthreads();

    int buf = 0;
    for (int c = 0; c < NC; c++) {
        bool more = (c + 1) < NC;
        if (more) {
            int k0 = (c + 1) * 16;
            xv = make_float4(0.f, 0.f, 0.f, 0.f);
            if (xok) xv = ((const float4*)X)[(size_t)(r0 + xrow) * (K / 4) + (k0 >> 2) + xkq];
#pragma unroll
            for (int q = 0; q < 2; q++) {
                int k = k0 + 2 * (wkh + 4 * q);
                wv[q][0] = W[(size_t)k * 128 + wcol];
                wv[q][1] = W[(size_t)(k + 1) * 128 + wcol];
            }
        }
        uint32_t ah[2][4], al[2][4];
#pragma unroll
        for (int mt = 0; mt < 2; mt++) {
            int rr = wr * 32 + mt * 16 + g;
            ah[mt][0] = Xh[buf][rr * XP + t];           al[mt][0] = Xl[buf][rr * XP + t];
            ah[mt][1] = Xh[buf][(rr + 8) * XP + t];     al[mt][1] = Xl[buf][(rr + 8) * XP + t];
            ah[mt][2] = Xh[buf][rr * XP + t + 4];       al[mt][2] = Xl[buf][rr * XP + t + 4];
            ah[mt][3] = Xh[buf][(rr + 8) * XP + t + 4]; al[mt][3] = Xl[buf][(rr + 8) * XP + t + 4];
        }
        uint32_t bh[4][2], bl[4][2];
#pragma unroll
        for (int nt = 0; nt < 4; nt++) {
            int cc = wc * 32 + nt * 8 + g;
            bh[nt][0] = Wh[buf][cc * XP + t];     bl[nt][0] = Wl[buf][cc * XP + t];
            bh[nt][1] = Wh[buf][cc * XP + t + 4]; bl[nt][1] = Wl[buf][cc * XP + t + 4];
        }
#pragma unroll
        for (int mt = 0; mt < 2; mt++)
#pragma unroll
            for (int nt = 0; nt < 4; nt++) {
                mma_bf16(acc[mt][nt], ah[mt], bh[nt]);
                mma_bf16(acc[mt][nt], ah[mt], bl[nt]);
                mma_bf16(acc[mt][nt], al[mt], bh[nt]);
            }
        if (more) {
            int nb2 = buf ^ 1;
            uint32_t h0, l0, h1, l1;
            split_pair(xv.x, xv.y, h0, l0);
            split_pair(xv.z, xv.w, h1, l1);
            int base = xrow * XP + xkq * 2;
            Xh[nb2][base] = h0; Xl[nb2][base] = l0;
            Xh[nb2][base + 1] = h1; Xl[nb2][base + 1] = l1;
#pragma unroll
            for (int q = 0; q < 2; q++) {
                uint32_t h, l;
                split_pair(wv[q][0], wv[q][1], h, l);
                int kp = wkh + 4 * q;
                Wh[nb2][wcol * XP + kp] = h;
                Wl[nb2][wcol * XP + kp] = l;
            }
            __syncthreads();
        }
        buf ^= 1;
    }
#pragma unroll
    for (int mt = 0; mt < 2; mt++) {
        int ra = r0 + wr * 32 + mt * 16 + g;
        int rb = ra + 8;
#pragma unroll
        for (int nt = 0; nt < 4; nt++) {
            int col = wc * 32 + nt * 8 + t * 2;
            if (ra < n) *(float2*)&Y[(size_t)ra * 128 + col] =
                make_float2(acc[mt][nt][0], acc[mt][nt][1]);
            if (rb < n) *(float2*)&Y[(size_t)rb * 128 + col] =
                make_float2(acc[mt][nt][2], acc[mt][nt][3]);
        }
    }
}

// ---------------- GEMM generic (layer 2, M=40) ----------------
template <int K, int M>
__global__ void k_gemm(const float* __restrict__ X, const float* __restrict__ W,
                       float* __restrict__ Y, int n) {
    __shared__ float xs[16 * K];
    int r0 = blockIdx.x * 16;
    for (int idx = threadIdx.x; idx < 16 * K / 4; idx += blockDim.x) {
        int r = r0 + idx / (K / 4);
        int k4 = idx % (K / 4);
        float4 v = make_float4(0.f, 0.f, 0.f, 0.f);
        if (r < n) v = ((const float4*)X)[(size_t)r * (K / 4) + k4];
        ((float4*)xs)[idx] = v;
    }
    __syncthreads();
    int c = threadIdx.x;
    if (c >= M) return;
    float acc[16];
#pragma unroll
    for (int r = 0; r < 16; r++) acc[r] = 0.f;
    for (int k = 0; k < K; k += 4) {
        float w0 = W[(k + 0) * M + c];
        float w1 = W[(k + 1) * M + c];
        float w2 = W[(k + 2) * M + c];
        float w3 = W[(k + 3) * M + c];
#pragma unroll
        for (int r = 0; r < 16; r++) {
            float4 xv = *(const float4*)&xs[r * K + k];
            acc[r] = fmaf(xv.x, w0, acc[r]);
            acc[r] = fmaf(xv.y, w1, acc[r]);
            acc[r] = fmaf(xv.z, w2, acc[r]);
            acc[r] = fmaf(xv.w, w3, acc[r]);
        }
    }
#pragma unroll
    for (int r = 0; r < 16; r++)
        if (r0 + r < n) Y[(size_t)(r0 + r) * M + c] = acc[r];
}

// ---------------- el/er ----------------
template <int H, int D>
__global__ void k_eler(const float* __restrict__ feat, const float* __restrict__ al,
                       const float* __restrict__ ar, int n) {
    int idx = blockIdx.x * blockDim.x + threadIdx.x;
    if (idx >= n * H) return;
    int nd = idx / H, h = idx % H;
    const float* f = feat + (size_t)nd * H * D + h * D;
    float sl = 0.f, sr = 0.f;
#pragma unroll
    for (int d = 0; d < D; d++) {
        float v = f[d];
        sl = fmaf(v, al[h * D + d], sl);
        sr = fmaf(v, ar[h * D + d], sr);
    }
    g_el[idx] = sl;
    g_er[idx] = sr;
}

__device__ __forceinline__ float leaky(float e) {
    return (e > 0.f) ? e : NEG_SLOPE * e;
}

// ---------------- aggregation H=4, D=32 (fp32 gather, deeper unroll) ----------------
#define CHUNK 128
__global__ __launch_bounds__(256) void k_agg4(const float* __restrict__ feat,
                                              const float* __restrict__ bias,
                                              float* __restrict__ out, int n) {
    __shared__ int   sh_s[8][CHUNK];
    __shared__ float sh_w[8][CHUNK * 4];
    int warp = (blockIdx.x * blockDim.x + threadIdx.x) >> 5;
    int lane = threadIdx.x & 31;
    int w8 = (threadIdx.x >> 5);
    if (warp >= n) return;
    int h = lane >> 3;
    int hh = lane & 3;
    int beg = g_off[warp], end = g_off[warp + 1];

    float4 er4 = ((const float4*)g_er)[warp];
    float er_hh = (hh == 0) ? er4.x : (hh == 1) ? er4.y : (hh == 2) ? er4.z : er4.w;

    const float4* feat4 = (const float4*)feat;
    float4 acc = make_float4(0.f, 0.f, 0.f, 0.f);
    float swl = 0.f;

    for (int c0 = beg; c0 < end; c0 += CHUNK) {
        int cnt = min(end - c0, CHUNK);
        __syncwarp();
        for (int j = (lane >> 2); j < cnt; j += 8) {
            int s = g_csr_src[c0 + j];
            if (hh == 0) sh_s[w8][j] = s;
            float e = g_el[s * 4 + hh];
            float w = __expf(leaky(e + er_hh));
            sh_w[w8][j * 4 + hh] = w;
            swl += w;
        }
        __syncwarp();
#pragma unroll 8
        for (int j = 0; j < cnt; j++) {
            int s = sh_s[w8][j];
            float w = sh_w[w8][j * 4 + h];
            float4 f = feat4[(size_t)s * 32 + lane];
            acc.x = fmaf(f.x, w, acc.x);
            acc.y = fmaf(f.y, w, acc.y);
            acc.z = fmaf(f.z, w, acc.z);
            acc.w = fmaf(f.w, w, acc.w);
        }
    }
#pragma unroll
    for (int o = 4; o < 32; o <<= 1) swl += __shfl_xor_sync(0xffffffffu, swl, o);
    float sw = __shfl_sync(0xffffffffu, swl, h);

    float inv = (end > beg) ? (1.0f / sw) : 0.f;
    float4 bv = ((const float4*)bias)[lane];
    float4 o;
    o.x = fmaxf(acc.x * inv + bv.x, 0.f);
    o.y = fmaxf(acc.y * inv + bv.y, 0.f);
    o.z = fmaxf(acc.z * inv + bv.z, 0.f);
    o.w = fmaxf(acc.w * inv + bv.w, 0.f);
    ((float4*)out)[(size_t)warp * 32 + lane] = o;
}

// ---------------- aggregation H=1, D=40 (layer 2) ----------------
__global__ __launch_bounds__(256) void k_agg1(const float* __restrict__ feat,
                                              const float* __restrict__ bias,
                                              float* __restrict__ out, int n) {
    __shared__ int   sh_s[8][CHUNK];
    __shared__ float sh_w[8][CHUNK];
    int warp = (blockIdx.x * blockDim.x + threadIdx.x) >> 5;
    int lane = threadIdx.x & 31;
    int w8 = (threadIdx.x >> 5);
    if (warp >= n) return;
    int beg = g_off[warp], end = g_off[warp + 1];
    float ern = g_er[warp];

    float acc0 = 0.f, acc1 = 0.f, swl = 0.f;
    for (int c0 = beg; c0 < end; c0 += CHUNK) {
        int cnt = min(end - c0, CHUNK);
        __syncwarp();
        for (int j = lane; j < cnt; j += 32) {
            int s = g_csr_src[c0 + j];
            sh_s[w8][j] = s;
            float w = __expf(leaky(g_el[s] + ern));
            sh_w[w8][j] = w;
            swl += w;
        }
        __syncwarp();
#pragma unroll 8
        for (int j = 0; j < cnt; j++) {
            int s = sh_s[w8][j];
            float w = sh_w[w8][j];
            const float* fs = feat + (size_t)s * 40;
            acc0 = fmaf(fs[lane], w, acc0);
            if (lane < 8) acc1 = fmaf(fs[32 + lane], w, acc1);
        }
    }
#pragma unroll
    for (int o = 16; o > 0; o >>= 1) swl += __shfl_xor_sync(0xffffffffu, swl, o);
    float inv = (end > beg) ? (1.0f / swl) : 0.f;
    out[(size_t)warp * 40 + lane] = acc0 * inv + bias[lane];
    if (lane < 8) out[(size_t)warp * 40 + 32 + lane] = acc1 * inv + bias[32 + lane];
}

// ---------------- launch ----------------
extern "C" void kernel_launch(void* const* d_in, const int* in_sizes, int n_in,
                              void* d_out, int out_size) {
    const float* x   = (const float*)d_in[0];
    const int*   src = (const int*)d_in[1];
    const int*   dst = (const int*)d_in[2];
    const float* W0  = (const float*)d_in[3];
    const float* al0 = (const float*)d_in[4];
    const float* ar0 = (const float*)d_in[5];
    const float* b0  = (const float*)d_in[6];
    const float* W1  = (const float*)d_in[7];
    const float* al1 = (const float*)d_in[8];
    const float* ar1 = (const float*)d_in[9];
    const float* b1  = (const float*)d_in[10];
    const float* W2  = (const float*)d_in[11];
    const float* al2 = (const float*)d_in[12];
    const float* ar2 = (const float*)d_in[13];
    const float* b2  = (const float*)d_in[14];

    int n = in_sizes[0] / 256;
    int E = in_sizes[1];
    float* out = (float*)d_out;

    float *feat, *x1, *x2;
    cudaGetSymbolAddress((void**)&feat, g_feat);
    cudaGetSymbolAddress((void**)&x1, g_x1);
    cudaGetSymbolAddress((void**)&x2, g_x2);

    int nb = (n + 1023) / 1024;
    int e4 = (E + 3) / 4;

    k_zero_cnt<<<(n + 255) / 256, 256>>>(n);
    k_count<<<(e4 + 255) / 256, 256>>>(dst, E);
    k_scan1<<<nb, 1024>>>(n);
    // launch 4: layer-0 GEMM (ncu window)
    k_gemm_tc<256><<<(n + 127) / 128, 512>>>(x, W0, feat, n);
    k_scan2<<<1, 32>>>(nb);
    k_scan3<<<(n + 255) / 256, 256>>>(n, E);
    k_scatter<<<(e4 + 255) / 256, 256>>>(src, dst, E);

    // layer 0
    k_eler<4, 32><<<(n * 4 + 255) / 256, 256>>>(feat, al0, ar0, n);
    k_agg4<<<(n + 7) / 8, 256>>>(feat, b0, x1, n);

    // layer 1
    k_gemm_tc<128><<<(n + 127) / 128, 512>>>(x1, W1, feat, n);
    k_eler<4, 32><<<(n * 4 + 255) / 256, 256>>>(feat, al1, ar1, n);
    k_agg4<<<(n + 7) / 8, 256>>>(feat, b1, x2, n);

    // layer 2
    k_gemm<128, 40><<<(n + 15) / 16, 128>>>(x2, W2, feat, n);
    k_eler<1, 40><<<(n + 255) / 256, 256>>>(feat, al2, ar2, n);
    k_agg1<<<(n + 7) / 8, 256>>>(feat, b2, out, n);
}

// round 15
// speedup vs baseline: 1.0004x; 1.0004x over previous
#include <cuda_runtime.h>
#include <cstddef>
#include <cstdint>

#define NEG_SLOPE 0.2f

static const int N_MAX = 50048;
static const int E_MAX = 1600000;
static const int NB_MAX = 64;

__device__ float g_feat[N_MAX * 128];
__device__ float g_x1[N_MAX * 128];
__device__ float g_x2[N_MAX * 128];
__device__ float g_el[N_MAX * 4];
__device__ float g_er[N_MAX * 4];
__device__ int   g_cnt[N_MAX];
__device__ int   g_off[N_MAX + 1];
__device__ int   g_cur[N_MAX];
__device__ int   g_blk[NB_MAX];
__device__ int   g_blkoff[NB_MAX];
__device__ int   g_csr_src[E_MAX];

// ---------------- CSR build ----------------
__global__ void k_zero_cnt(int n) {
    int i = blockIdx.x * blockDim.x + threadIdx.x;
    if (i < n) g_cnt[i] = 0;
}

__global__ void k_count(const int* __restrict__ dst, int E) {
    int e = blockIdx.x * blockDim.x + threadIdx.x;
    if (e < E) atomicAdd(&g_cnt[dst[e]], 1);
}

__global__ void k_scan1(int n) {
    __shared__ int sh[1024];
    int tid = threadIdx.x;
    int i = blockIdx.x * 1024 + tid;
    int v = (i < n) ? g_cnt[i] : 0;
    sh[tid] = v;
    __syncthreads();
#pragma unroll
    for (int o = 1; o < 1024; o <<= 1) {
        int t = (tid >= o) ? sh[tid - o] : 0;
        __syncthreads();
        sh[tid] += t;
        __syncthreads();
    }
    if (i <= n) g_off[i] = sh[tid] - v;
    if (tid == 1023) g_blk[blockIdx.x] = sh[1023];
}

__global__ void k_scan2(int nb) {
    int lane = threadIdx.x;
    int v0 = (lane < nb) ? g_blk[lane] : 0;
    int v1 = (lane + 32 < nb) ? g_blk[lane + 32] : 0;
    int s0 = v0, s1 = v1;
#pragma unroll
    for (int o = 1; o < 32; o <<= 1) {
        int t0 = __shfl_up_sync(0xffffffffu, s0, o);
        int t1 = __shfl_up_sync(0xffffffffu, s1, o);
        if (lane >= o) { s0 += t0; s1 += t1; }
    }
    int tot0 = __shfl_sync(0xffffffffu, s0, 31);
    if (lane < nb) g_blkoff[lane] = s0 - v0;
    if (lane + 32 < nb) g_blkoff[lane + 32] = tot0 + s1 - v1;
}

__global__ void k_scan3(int n, int E) {
    int i = blockIdx.x * blockDim.x + threadIdx.x;
    if (i < n) {
        int o = g_off[i] + g_blkoff[i >> 10];
        g_off[i] = o;
        g_cur[i] = o;
    }
    if (i == 0) g_off[n] = E;
}

__global__ void k_scatter(const int* __restrict__ src, const int* __restrict__ dst, int E) {
    int e = blockIdx.x * blockDim.x + threadIdx.x;
    if (e < E) {
        int p = atomicAdd(&g_cur[dst[e]], 1);
        g_csr_src[p] = src[e];
    }
}

// ---------------- bf16 split helpers ----------------
__device__ __forceinline__ void split_pair(float x0, float x1, uint32_t& hi, uint32_t& lo) {
    uint32_t u0 = __float_as_uint(x0), u1 = __float_as_uint(x1);
    hi = __byte_perm(u0, u1, 0x7632);
    float l0 = x0 - __uint_as_float(u0 & 0xFFFF0000u);
    float l1 = x1 - __uint_as_float(u1 & 0xFFFF0000u);
    asm("cvt.rn.bf16x2.f32 %0, %1, %2;" : "=r"(lo) : "f"(l1), "f"(l0));
}

__device__ __forceinline__ void mma_bf16(float* d, const uint32_t* a, const uint32_t* b) {
    asm volatile(
        "mma.sync.aligned.m16n8k16.row.col.f32.bf16.bf16.f32 "
        "{%0,%1,%2,%3}, {%4,%5,%6,%7}, {%8,%9}, {%0,%1,%2,%3};"
        : "+f"(d[0]), "+f"(d[1]), "+f"(d[2]), "+f"(d[3])
        : "r"(a[0]), "r"(a[1]), "r"(a[2]), "r"(a[3]), "r"(b[0]), "r"(b[1]));
}

// ---------------- GEMM (M=128): bf16 TC, 2-term split, double-buffered ----------------
#define XP 9
template <int K>
__global__ __launch_bounds__(512) void k_gemm_tc(const float* __restrict__ X,
                                                 const float* __restrict__ W,
                                                 float* __restrict__ Y, int n) {
    __shared__ uint32_t Xh[2][128 * XP], Xl[2][128 * XP];
    __shared__ uint32_t Wh[2][128 * XP], Wl[2][128 * XP];
    int tid = threadIdx.x;
    int w = tid >> 5;
    int lane = tid & 31;
    int g = lane >> 2;
    int t = lane & 3;
    int wr = w & 3;
    int wc = w >> 2;
    int r0 = blockIdx.x * 128;

    float acc[2][4][4];
#pragma unroll
    for (int mt = 0; mt < 2; mt++)
#pragma unroll
        for (int nt = 0; nt < 4; nt++)
#pragma unroll
            for (int q = 0; q < 4; q++) acc[mt][nt][q] = 0.f;

    int xrow = tid >> 2;
    int xkq = tid & 3;
    bool xok = (r0 + xrow) < n;
    int wcol = tid & 127;
    int wkh = tid >> 7;

    const int NC = K / 16;

    float4 xv = make_float4(0.f, 0.f, 0.f, 0.f);
    if (xok) xv = ((const float4*)X)[(size_t)(r0 + xrow) * (K / 4) + xkq];
    float wv[2][2];
#pragma unroll
    for (int q = 0; q < 2; q++) {
        int k = 2 * (wkh + 4 * q);
        wv[q][0] = W[(size_t)k * 128 + wcol];
        wv[q][1] = W[(size_t)(k + 1) * 128 + wcol];
    }
    {
        uint32_t h0, l0, h1, l1;
        split_pair(xv.x, xv.y, h0, l0);
        split_pair(xv.z, xv.w, h1, l1);
        int base = xrow * XP + xkq * 2;
        Xh[0][base] = h0; Xl[0][base] = l0;
        Xh[0][base + 1] = h1; Xl[0][base + 1] = l1;
#pragma unroll
        for (int q = 0; q < 2; q++) {
            uint32_t h, l;
            split_pair(wv[q][0], wv[q][1], h, l);
            int kp = wkh + 4 * q;
            Wh[0][wcol * XP + kp] = h;
            Wl[0][wcol * XP + kp] = l;
        }
    }
    __syncthreads();

    int buf = 0;
    for (int c = 0; c < NC; c++) {
        bool more = (c + 1) < NC;
        if (more) {
            int k0 = (c + 1) * 16;
            xv = make_float4(0.f, 0.f, 0.f, 0.f);
            if (xok) xv = ((const float4*)X)[(size_t)(r0 + xrow) * (K / 4) + (k0 >> 2) + xkq];
#pragma unroll
            for (int q = 0; q < 2; q++) {
                int k = k0 + 2 * (wkh + 4 * q);
                wv[q][0] = W[(size_t)k * 128 + wcol];
                wv[q][1] = W[(size_t)(k + 1) * 128 + wcol];
            }
        }
        uint32_t ah[2][4], al[2][4];
#pragma unroll
        for (int mt = 0; mt < 2; mt++) {
            int rr = wr * 32 + mt * 16 + g;
            ah[mt][0] = Xh[buf][rr * XP + t];           al[mt][0] = Xl[buf][rr * XP + t];
            ah[mt][1] = Xh[buf][(rr + 8) * XP + t];     al[mt][1] = Xl[buf][(rr + 8) * XP + t];
            ah[mt][2] = Xh[buf][rr * XP + t + 4];       al[mt][2] = Xl[buf][rr * XP + t + 4];
            ah[mt][3] = Xh[buf][(rr + 8) * XP + t + 4]; al[mt][3] = Xl[buf][(rr + 8) * XP + t + 4];
        }
        uint32_t bh[4][2], bl[4][2];
#pragma unroll
        for (int nt = 0; nt < 4; nt++) {
            int cc = wc * 32 + nt * 8 + g;
            bh[nt][0] = Wh[buf][cc * XP + t];     bl[nt][0] = Wl[buf][cc * XP + t];
            bh[nt][1] = Wh[buf][cc * XP + t + 4]; bl[nt][1] = Wl[buf][cc * XP + t + 4];
        }
#pragma unroll
        for (int mt = 0; mt < 2; mt++)
#pragma unroll
            for (int nt = 0; nt < 4; nt++) {
                mma_bf16(acc[mt][nt], ah[mt], bh[nt]);
                mma_bf16(acc[mt][nt], ah[mt], bl[nt]);
                mma_bf16(acc[mt][nt], al[mt], bh[nt]);
            }
        if (more) {
            int nb2 = buf ^ 1;
            uint32_t h0, l0, h1, l1;
            split_pair(xv.x, xv.y, h0, l0);
            split_pair(xv.z, xv.w, h1, l1);
            int base = xrow * XP + xkq * 2;
            Xh[nb2][base] = h0; Xl[nb2][base] = l0;
            Xh[nb2][base + 1] = h1; Xl[nb2][base + 1] = l1;
#pragma unroll
            for (int q = 0; q < 2; q++) {
                uint32_t h, l;
                split_pair(wv[q][0], wv[q][1], h, l);
                int kp = wkh + 4 * q;
                Wh[nb2][wcol * XP + kp] = h;
                Wl[nb2][wcol * XP + kp] = l;
            }
            __syncthreads();
        }
        buf ^= 1;
    }
#pragma unroll
    for (int mt = 0; mt < 2; mt++) {
        int ra = r0 + wr * 32 + mt * 16 + g;
        int rb = ra + 8;
#pragma unroll
        for (int nt = 0; nt < 4; nt++) {
            int col = wc * 32 + nt * 8 + t * 2;
            if (ra < n) *(float2*)&Y[(size_t)ra * 128 + col] =
                make_float2(acc[mt][nt][0], acc[mt][nt][1]);
            if (rb < n) *(float2*)&Y[(size_t)rb * 128 + col] =
                make_float2(acc[mt][nt][2], acc[mt][nt][3]);
        }
    }
}

// ---------------- GEMM generic (layer 2, M=40) ----------------
template <int K, int M>
__global__ void k_gemm(const float* __restrict__ X, const float* __restrict__ W,
                       float* __restrict__ Y, int n) {
    __shared__ float xs[16 * K];
    int r0 = blockIdx.x * 16;
    for (int idx = threadIdx.x; idx < 16 * K / 4; idx += blockDim.x) {
        int r = r0 + idx / (K / 4);
        int k4 = idx % (K / 4);
        float4 v = make_float4(0.f, 0.f, 0.f, 0.f);
        if (r < n) v = ((const float4*)X)[(size_t)r * (K / 4) + k4];
        ((float4*)xs)[idx] = v;
    }
    __syncthreads();
    int c = threadIdx.x;
    if (c >= M) return;
    float acc[16];
#pragma unroll
    for (int r = 0; r < 16; r++) acc[r] = 0.f;
    for (int k = 0; k < K; k += 4) {
        float w0 = W[(k + 0) * M + c];
        float w1 = W[(k + 1) * M + c];
        float w2 = W[(k + 2) * M + c];
        float w3 = W[(k + 3) * M + c];
#pragma unroll
        for (int r = 0; r < 16; r++) {
            float4 xv = *(const float4*)&xs[r * K + k];
            acc[r] = fmaf(xv.x, w0, acc[r]);
            acc[r] = fmaf(xv.y, w1, acc[r]);
            acc[r] = fmaf(xv.z, w2, acc[r]);
            acc[r] = fmaf(xv.w, w3, acc[r]);
        }
    }
#pragma unroll
    for (int r = 0; r < 16; r++)
        if (r0 + r < n) Y[(size_t)(r0 + r) * M + c] = acc[r];
}

// ---------------- el/er ----------------
template <int H, int D>
__global__ void k_eler(const float* __restrict__ feat, const float* __restrict__ al,
                       const float* __restrict__ ar, int n) {
    int idx = blockIdx.x * blockDim.x + threadIdx.x;
    if (idx >= n * H) return;
    int nd = idx / H, h = idx % H;
    const float* f = feat + (size_t)nd * H * D + h * D;
    float sl = 0.f, sr = 0.f;
#pragma unroll
    for (int d = 0; d < D; d++) {
        float v = f[d];
        sl = fmaf(v, al[h * D + d], sl);
        sr = fmaf(v, ar[h * D + d], sr);
    }
    g_el[idx] = sl;
    g_er[idx] = sr;
}

__device__ __forceinline__ float leaky(float e) {
    return (e > 0.f) ? e : NEG_SLOPE * e;
}

// ---------------- aggregation H=4, D=32: TWO warps per node ----------------
// Block 256 = 8 warps = 4 nodes x 2 warps. Each warp aggregates half the edge
// list (halves the per-warp serial latency chain); partials combined via smem.
#define CHUNK 128
__global__ __launch_bounds__(256) void k_agg4(const float* __restrict__ feat,
                                              const float* __restrict__ bias,
                                              float* __restrict__ out, int n) {
    __shared__ int    sh_s[8][CHUNK];
    __shared__ float  sh_w[8][CHUNK * 4];
    __shared__ float4 comb[8][32];
    __shared__ float  combw[8][4];
    int wib = threadIdx.x >> 5;            // warp in block 0..7
    int lane = threadIdx.x & 31;
    int node = blockIdx.x * 4 + (wib >> 1);
    int half = wib & 1;
    bool active = node < n;
    int h = lane >> 3;
    int hh = lane & 3;

    int beg = 0, end = 0;
    if (active) { beg = g_off[node]; end = g_off[node + 1]; }
    int len = end - beg;
    int mid = beg + ((len + 1) >> 1);
    int mybeg = half ? mid : beg;
    int myend = half ? end : mid;

    float4 er4 = make_float4(0.f, 0.f, 0.f, 0.f);
    if (active) er4 = ((const float4*)g_er)[node];
    float er_hh = (hh == 0) ? er4.x : (hh == 1) ? er4.y : (hh == 2) ? er4.z : er4.w;

    const float4* feat4 = (const float4*)feat;
    float4 acc = make_float4(0.f, 0.f, 0.f, 0.f);
    float swl = 0.f;

    for (int c0 = mybeg; c0 < myend; c0 += CHUNK) {
        int cnt = min(myend - c0, CHUNK);
        __syncwarp();
        for (int j = (lane >> 2); j < cnt; j += 8) {
            int s = g_csr_src[c0 + j];
            if (hh == 0) sh_s[wib][j] = s;
            float e = g_el[s * 4 + hh];
            float w = __expf(leaky(e + er_hh));
            sh_w[wib][j * 4 + hh] = w;
            swl += w;
        }
        __syncwarp();
#pragma unroll 4
        for (int j = 0; j < cnt; j++) {
            int s = sh_s[wib][j];
            float w = sh_w[wib][j * 4 + h];
            float4 f = feat4[(size_t)s * 32 + lane];
            acc.x = fmaf(f.x, w, acc.x);
            acc.y = fmaf(f.y, w, acc.y);
            acc.z = fmaf(f.z, w, acc.z);
            acc.w = fmaf(f.w, w, acc.w);
        }
    }
    // per-warp head sums: after xor over 4,8,16 every lane has total for head lane&3
#pragma unroll
    for (int o = 4; o < 32; o <<= 1) swl += __shfl_xor_sync(0xffffffffu, swl, o);
    if (lane < 4) combw[wib][lane] = swl;
    comb[wib][lane] = acc;
    __syncthreads();

    if (half == 0 && active) {
        float4 p = comb[wib + 1][lane];
        acc.x += p.x; acc.y += p.y; acc.z += p.z; acc.w += p.w;
        float sw = combw[wib][h] + combw[wib + 1][h];
        float inv = (len > 0) ? (1.0f / sw) : 0.f;
        float4 bv = ((const float4*)bias)[lane];
        float4 o;
        o.x = fmaxf(acc.x * inv + bv.x, 0.f);
        o.y = fmaxf(acc.y * inv + bv.y, 0.f);
        o.z = fmaxf(acc.z * inv + bv.z, 0.f);
        o.w = fmaxf(acc.w * inv + bv.w, 0.f);
        ((float4*)out)[(size_t)node * 32 + lane] = o;
    }
}

// ---------------- aggregation H=1, D=40 (layer 2) ----------------
__global__ __launch_bounds__(256) void k_agg1(const float* __restrict__ feat,
                                              const float* __restrict__ bias,
                                              float* __restrict__ out, int n) {
    __shared__ int   sh_s[8][CHUNK];
    __shared__ float sh_w[8][CHUNK];
    int warp = (blockIdx.x * blockDim.x + threadIdx.x) >> 5;
    int lane = threadIdx.x & 31;
    int w8 = (threadIdx.x >> 5);
    if (warp >= n) return;
    int beg = g_off[warp], end = g_off[warp + 1];
    float ern = g_er[warp];

    float acc0 = 0.f, acc1 = 0.f, swl = 0.f;
    for (int c0 = beg; c0 < end; c0 += CHUNK) {
        int cnt = min(end - c0, CHUNK);
        __syncwarp();
        for (int j = lane; j < cnt; j += 32) {
            int s = g_csr_src[c0 + j];
            sh_s[w8][j] = s;
            float w = __expf(leaky(g_el[s] + ern));
            sh_w[w8][j] = w;
            swl += w;
        }
        __syncwarp();
#pragma unroll 4
        for (int j = 0; j < cnt; j++) {
            int s = sh_s[w8][j];
            float w = sh_w[w8][j];
            const float* fs = feat + (size_t)s * 40;
            acc0 = fmaf(fs[lane], w, acc0);
            if (lane < 8) acc1 = fmaf(fs[32 + lane], w, acc1);
        }
    }
#pragma unroll
    for (int o = 16; o > 0; o >>= 1) swl += __shfl_xor_sync(0xffffffffu, swl, o);
    float inv = (end > beg) ? (1.0f / swl) : 0.f;
    out[(size_t)warp * 40 + lane] = acc0 * inv + bias[lane];
    if (lane < 8) out[(size_t)warp * 40 + 32 + lane] = acc1 * inv + bias[32 + lane];
}

// ---------------- launch ----------------
extern "C" void kernel_launch(void* const* d_in, const int* in_sizes, int n_in,
                              void* d_out, int out_size) {
    const float* x   = (const float*)d_in[0];
    const int*   src = (const int*)d_in[1];
    const int*   dst = (const int*)d_in[2];
    const float* W0  = (const float*)d_in[3];
    const float* al0 = (const float*)d_in[4];
    const float* ar0 = (const float*)d_in[5];
    const float* b0  = (const float*)d_in[6];
    const float* W1  = (const float*)d_in[7];
    const float* al1 = (const float*)d_in[8];
    const float* ar1 = (const float*)d_in[9];
    const float* b1  = (const float*)d_in[10];
    const float* W2  = (const float*)d_in[11];
    const float* al2 = (const float*)d_in[12];
    const float* ar2 = (const float*)d_in[13];
    const float* b2  = (const float*)d_in[14];

    int n = in_sizes[0] / 256;
    int E = in_sizes[1];
    float* out = (float*)d_out;

    float *feat, *x1, *x2;
    cudaGetSymbolAddress((void**)&feat, g_feat);
    cudaGetSymbolAddress((void**)&x1, g_x1);
    cudaGetSymbolAddress((void**)&x2, g_x2);

    int nb = (n + 1023) / 1024;

    k_zero_cnt<<<(n + 255) / 256, 256>>>(n);
    k_count<<<(E + 255) / 256, 256>>>(dst, E);
    k_scan1<<<nb, 1024>>>(n);
    // launch 4: layer-0 GEMM (ncu window)
    k_gemm_tc<256><<<(n + 127) / 128, 512>>>(x, W0, feat, n);
    k_scan2<<<1, 32>>>(nb);
    k_scan3<<<(n + 255) / 256, 256>>>(n, E);
    k_scatter<<<(E + 255) / 256, 256>>>(src, dst, E);

    // layer 0
    k_eler<4, 32><<<(n * 4 + 255) / 256, 256>>>(feat, al0, ar0, n);
    k_agg4<<<(n + 3) / 4, 256>>>(feat, b0, x1, n);

    // layer 1
    k_gemm_tc<128><<<(n + 127) / 128, 512>>>(x1, W1, feat, n);
    k_eler<4, 32><<<(n * 4 + 255) / 256, 256>>>(feat, al1, ar1, n);
    k_agg4<<<(n + 3) / 4, 256>>>(feat, b1, x2, n);

    // layer 2
    k_gemm<128, 40><<<(n + 15) / 16, 128>>>(x2, W2, feat, n);
    k_eler<1, 40><<<(n + 255) / 256, 256>>>(feat, al2, ar2, n);
    k_agg1<<<(n + 7) / 8, 256>>>(feat, b2, out, n);
}

// round 16
// speedup vs baseline: 1.1859x; 1.1855x over previous
#include <cuda_runtime.h>
#include <cstddef>
#include <cstdint>

#define NEG_SLOPE 0.2f

static const int N_MAX = 50048;
static const int E_MAX = 1600000;
static const int NB_MAX = 64;

__device__ float g_feat[N_MAX * 128];
__device__ float g_x1[N_MAX * 128];
__device__ float g_x2[N_MAX * 128];
__device__ float g_el[N_MAX * 4];
__device__ float g_er[N_MAX * 4];
__device__ int   g_cnt[N_MAX];
__device__ int   g_off[N_MAX + 1];
__device__ int   g_cur[N_MAX];
__device__ int   g_blk[NB_MAX];
__device__ int   g_blkoff[NB_MAX];
__device__ int   g_csr_src[E_MAX];

// ---------------- CSR build ----------------
__global__ void k_zero_cnt(int n) {
    int i = blockIdx.x * blockDim.x + threadIdx.x;
    if (i < n) g_cnt[i] = 0;
}

__global__ void k_count(const int* __restrict__ dst, int E) {
    int e = blockIdx.x * blockDim.x + threadIdx.x;
    if (e < E) atomicAdd(&g_cnt[dst[e]], 1);
}

__global__ void k_scan1(int n) {
    __shared__ int sh[1024];
    int tid = threadIdx.x;
    int i = blockIdx.x * 1024 + tid;
    int v = (i < n) ? g_cnt[i] : 0;
    sh[tid] = v;
    __syncthreads();
#pragma unroll
    for (int o = 1; o < 1024; o <<= 1) {
        int t = (tid >= o) ? sh[tid - o] : 0;
        __syncthreads();
        sh[tid] += t;
        __syncthreads();
    }
    if (i <= n) g_off[i] = sh[tid] - v;
    if (tid == 1023) g_blk[blockIdx.x] = sh[1023];
}

__global__ void k_scan2(int nb) {
    int lane = threadIdx.x;
    int v0 = (lane < nb) ? g_blk[lane] : 0;
    int v1 = (lane + 32 < nb) ? g_blk[lane + 32] : 0;
    int s0 = v0, s1 = v1;
#pragma unroll
    for (int o = 1; o < 32; o <<= 1) {
        int t0 = __shfl_up_sync(0xffffffffu, s0, o);
        int t1 = __shfl_up_sync(0xffffffffu, s1, o);
        if (lane >= o) { s0 += t0; s1 += t1; }
    }
    int tot0 = __shfl_sync(0xffffffffu, s0, 31);
    if (lane < nb) g_blkoff[lane] = s0 - v0;
    if (lane + 32 < nb) g_blkoff[lane + 32] = tot0 + s1 - v1;
}

__global__ void k_scan3(int n, int E) {
    int i = blockIdx.x * blockDim.x + threadIdx.x;
    if (i < n) {
        int o = g_off[i] + g_blkoff[i >> 10];
        g_off[i] = o;
        g_cur[i] = o;
    }
    if (i == 0) g_off[n] = E;
}

__global__ void k_scatter(const int* __restrict__ src, const int* __restrict__ dst, int E) {
    int e = blockIdx.x * blockDim.x + threadIdx.x;
    if (e < E) {
        int p = atomicAdd(&g_cur[dst[e]], 1);
        g_csr_src[p] = src[e];
    }
}

// ---------------- bf16 split helpers ----------------
__device__ __forceinline__ void split_pair(float x0, float x1, uint32_t& hi, uint32_t& lo) {
    uint32_t u0 = __float_as_uint(x0), u1 = __float_as_uint(x1);
    hi = __byte_perm(u0, u1, 0x7632);
    float l0 = x0 - __uint_as_float(u0 & 0xFFFF0000u);
    float l1 = x1 - __uint_as_float(u1 & 0xFFFF0000u);
    asm("cvt.rn.bf16x2.f32 %0, %1, %2;" : "=r"(lo) : "f"(l1), "f"(l0));
}

__device__ __forceinline__ void mma_bf16(float* d, const uint32_t* a, const uint32_t* b) {
    asm volatile(
        "mma.sync.aligned.m16n8k16.row.col.f32.bf16.bf16.f32 "
        "{%0,%1,%2,%3}, {%4,%5,%6,%7}, {%8,%9}, {%0,%1,%2,%3};"
        : "+f"(d[0]), "+f"(d[1]), "+f"(d[2]), "+f"(d[3])
        : "r"(a[0]), "r"(a[1]), "r"(a[2]), "r"(a[3]), "r"(b[0]), "r"(b[1]));
}

// ---------------- GEMM (M=128): bf16 TC, 2-term split, double-buffered ----------------
#define XP 9
template <int K>
__global__ __launch_bounds__(512) void k_gemm_tc(const float* __restrict__ X,
                                                 const float* __restrict__ W,
                                                 float* __restrict__ Y, int n) {
    __shared__ uint32_t Xh[2][128 * XP], Xl[2][128 * XP];
    __shared__ uint32_t Wh[2][128 * XP], Wl[2][128 * XP];
    int tid = threadIdx.x;
    int w = tid >> 5;
    int lane = tid & 31;
    int g = lane >> 2;
    int t = lane & 3;
    int wr = w & 3;
    int wc = w >> 2;
    int r0 = blockIdx.x * 128;

    float acc[2][4][4];
#pragma unroll
    for (int mt = 0; mt < 2; mt++)
#pragma unroll
        for (int nt = 0; nt < 4; nt++)
#pragma unroll
            for (int q = 0; q < 4; q++) acc[mt][nt][q] = 0.f;

    int xrow = tid >> 2;
    int xkq = tid & 3;
    bool xok = (r0 + xrow) < n;
    int wcol = tid & 127;
    int wkh = tid >> 7;

    const int NC = K / 16;

    float4 xv = make_float4(0.f, 0.f, 0.f, 0.f);
    if (xok) xv = ((const float4*)X)[(size_t)(r0 + xrow) * (K / 4) + xkq];
    float wv[2][2];
#pragma unroll
    for (int q = 0; q < 2; q++) {
        int k = 2 * (wkh + 4 * q);
        wv[q][0] = W[(size_t)k * 128 + wcol];
        wv[q][1] = W[(size_t)(k + 1) * 128 + wcol];
    }
    {
        uint32_t h0, l0, h1, l1;
        split_pair(xv.x, xv.y, h0, l0);
        split_pair(xv.z, xv.w, h1, l1);
        int base = xrow * XP + xkq * 2;
        Xh[0][base] = h0; Xl[0][base] = l0;
        Xh[0][base + 1] = h1; Xl[0][base + 1] = l1;
#pragma unroll
        for (int q = 0; q < 2; q++) {
            uint32_t h, l;
            split_pair(wv[q][0], wv[q][1], h, l);
            int kp = wkh + 4 * q;
            Wh[0][wcol * XP + kp] = h;
            Wl[0][wcol * XP + kp] = l;
        }
    }
    __syncthreads();

    int buf = 0;
    for (int c = 0; c < NC; c++) {
        bool more = (c + 1) < NC;
        if (more) {
            int k0 = (c + 1) * 16;
            xv = make_float4(0.f, 0.f, 0.f, 0.f);
            if (xok) xv = ((const float4*)X)[(size_t)(r0 + xrow) * (K / 4) + (k0 >> 2) + xkq];
#pragma unroll
            for (int q = 0; q < 2; q++) {
                int k = k0 + 2 * (wkh + 4 * q);
                wv[q][0] = W[(size_t)k * 128 + wcol];
                wv[q][1] = W[(size_t)(k + 1) * 128 + wcol];
            }
        }
        uint32_t ah[2][4], al[2][4];
#pragma unroll
        for (int mt = 0; mt < 2; mt++) {
            int rr = wr * 32 + mt * 16 + g;
            ah[mt][0] = Xh[buf][rr * XP + t];           al[mt][0] = Xl[buf][rr * XP + t];
            ah[mt][1] = Xh[buf][(rr + 8) * XP + t];     al[mt][1] = Xl[buf][(rr + 8) * XP + t];
            ah[mt][2] = Xh[buf][rr * XP + t + 4];       al[mt][2] = Xl[buf][rr * XP + t + 4];
            ah[mt][3] = Xh[buf][(rr + 8) * XP + t + 4]; al[mt][3] = Xl[buf][(rr + 8) * XP + t + 4];
        }
        uint32_t bh[4][2], bl[4][2];
#pragma unroll
        for (int nt = 0; nt < 4; nt++) {
            int cc = wc * 32 + nt * 8 + g;
            bh[nt][0] = Wh[buf][cc * XP + t];     bl[nt][0] = Wl[buf][cc * XP + t];
            bh[nt][1] = Wh[buf][cc * XP + t + 4]; bl[nt][1] = Wl[buf][cc * XP + t + 4];
        }
#pragma unroll
        for (int mt = 0; mt < 2; mt++)
#pragma unroll
            for (int nt = 0; nt < 4; nt++) {
                mma_bf16(acc[mt][nt], ah[mt], bh[nt]);
                mma_bf16(acc[mt][nt], ah[mt], bl[nt]);
                mma_bf16(acc[mt][nt], al[mt], bh[nt]);
            }
        if (more) {
            int nb2 = buf ^ 1;
            uint32_t h0, l0, h1, l1;
            split_pair(xv.x, xv.y, h0, l0);
            split_pair(xv.z, xv.w, h1, l1);
            int base = xrow * XP + xkq * 2;
            Xh[nb2][base] = h0; Xl[nb2][base] = l0;
            Xh[nb2][base + 1] = h1; Xl[nb2][base + 1] = l1;
#pragma unroll
            for (int q = 0; q < 2; q++) {
                uint32_t h, l;
                split_pair(wv[q][0], wv[q][1], h, l);
                int kp = wkh + 4 * q;
                Wh[nb2][wcol * XP + kp] = h;
                Wl[nb2][wcol * XP + kp] = l;
            }
            __syncthreads();
        }
        buf ^= 1;
    }
#pragma unroll
    for (int mt = 0; mt < 2; mt++) {
        int ra = r0 + wr * 32 + mt * 16 + g;
        int rb = ra + 8;
#pragma unroll
        for (int nt = 0; nt < 4; nt++) {
            int col = wc * 32 + nt * 8 + t * 2;
            if (ra < n) *(float2*)&Y[(size_t)ra * 128 + col] =
                make_float2(acc[mt][nt][0], acc[mt][nt][1]);
            if (rb < n) *(float2*)&Y[(size_t)rb * 128 + col] =
                make_float2(acc[mt][nt][2], acc[mt][nt][3]);
        }
    }
}

// ---------------- GEMM generic (layer 2, M=40) ----------------
template <int K, int M>
__global__ void k_gemm(const float* __restrict__ X, const float* __restrict__ W,
                       float* __restrict__ Y, int n) {
    __shared__ float xs[16 * K];
    int r0 = blockIdx.x * 16;
    for (int idx = threadIdx.x; idx < 16 * K / 4; idx += blockDim.x) {
        int r = r0 + idx / (K / 4);
        int k4 = idx % (K / 4);
        float4 v = make_float4(0.f, 0.f, 0.f, 0.f);
        if (r < n) v = ((const float4*)X)[(size_t)r * (K / 4) + k4];
        ((float4*)xs)[idx] = v;
    }
    __syncthreads();
    int c = threadIdx.x;
    if (c >= M) return;
    float acc[16];
#pragma unroll
    for (int r = 0; r < 16; r++) acc[r] = 0.f;
    for (int k = 0; k < K; k += 4) {
        float w0 = W[(k + 0) * M + c];
        float w1 = W[(k + 1) * M + c];
        float w2 = W[(k + 2) * M + c];
        float w3 = W[(k + 3) * M + c];
#pragma unroll
        for (int r = 0; r < 16; r++) {
            float4 xv = *(const float4*)&xs[r * K + k];
            acc[r] = fmaf(xv.x, w0, acc[r]);
            acc[r] = fmaf(xv.y, w1, acc[r]);
            acc[r] = fmaf(xv.z, w2, acc[r]);
            acc[r] = fmaf(xv.w, w3, acc[r]);
        }
    }
#pragma unroll
    for (int r = 0; r < 16; r++)
        if (r0 + r < n) Y[(size_t)(r0 + r) * M + c] = acc[r];
}

// ---------------- el/er: COALESCED warp-per-node ----------------
// H=4, D=32: lane loads float4 of the 128-float row (4 wavefronts/row).
// ((float4*)al)[lane] == al[head=lane>>3][dims (lane&7)*4..+4] — exact fragment match.
__global__ __launch_bounds__(256) void k_eler4(const float* __restrict__ feat,
                                               const float* __restrict__ al,
                                               const float* __restrict__ ar, int n) {
    int warp = (blockIdx.x * blockDim.x + threadIdx.x) >> 5;
    int lane = threadIdx.x & 31;
    if (warp >= n) return;
    float4 f = ((const float4*)feat)[(size_t)warp * 32 + lane];
    float4 a = ((const float4*)al)[lane];
    float4 r = ((const float4*)ar)[lane];
    float sl = f.x * a.x + f.y * a.y + f.z * a.z + f.w * a.w;
    float sr = f.x * r.x + f.y * r.y + f.z * r.z + f.w * r.w;
#pragma unroll
    for (int o = 1; o < 8; o <<= 1) {
        sl += __shfl_xor_sync(0xffffffffu, sl, o);
        sr += __shfl_xor_sync(0xffffffffu, sr, o);
    }
    if ((lane & 7) == 0) {
        int h = lane >> 3;
        g_el[warp * 4 + h] = sl;
        g_er[warp * 4 + h] = sr;
    }
}

// H=1, D=40: 10 active lanes per node, full-warp reduce.
__global__ __launch_bounds__(256) void k_eler1(const float* __restrict__ feat,
                                               const float* __restrict__ al,
                                               const float* __restrict__ ar, int n) {
    int warp = (blockIdx.x * blockDim.x + threadIdx.x) >> 5;
    int lane = threadIdx.x & 31;
    if (warp >= n) return;
    float sl = 0.f, sr = 0.f;
    if (lane < 10) {
        float4 f = ((const float4*)feat)[(size_t)warp * 10 + lane];
        float4 a = ((const float4*)al)[lane];
        float4 r = ((const float4*)ar)[lane];
        sl = f.x * a.x + f.y * a.y + f.z * a.z + f.w * a.w;
        sr = f.x * r.x + f.y * r.y + f.z * r.z + f.w * r.w;
    }
#pragma unroll
    for (int o = 16; o > 0; o >>= 1) {
        sl += __shfl_xor_sync(0xffffffffu, sl, o);
        sr += __shfl_xor_sync(0xffffffffu, sr, o);
    }
    if (lane == 0) {
        g_el[warp] = sl;
        g_er[warp] = sr;
    }
}

__device__ __forceinline__ float leaky(float e) {
    return (e > 0.f) ? e : NEG_SLOPE * e;
}

// ---------------- aggregation H=4, D=32 (exact R10 version) ----------------
#define CHUNK 128
__global__ __launch_bounds__(256) void k_agg4(const float* __restrict__ feat,
                                              const float* __restrict__ bias,
                                              float* __restrict__ out, int n) {
    __shared__ int   sh_s[8][CHUNK];
    __shared__ float sh_w[8][CHUNK * 4];
    int warp = (blockIdx.x * blockDim.x + threadIdx.x) >> 5;
    int lane = threadIdx.x & 31;
    int w8 = (threadIdx.x >> 5);
    if (warp >= n) return;
    int h = lane >> 3;
    int hh = lane & 3;
    int beg = g_off[warp], end = g_off[warp + 1];

    float4 er4 = ((const float4*)g_er)[warp];
    float er_hh = (hh == 0) ? er4.x : (hh == 1) ? er4.y : (hh == 2) ? er4.z : er4.w;

    const float4* feat4 = (const float4*)feat;
    float4 acc = make_float4(0.f, 0.f, 0.f, 0.f);
    float swl = 0.f;

    for (int c0 = beg; c0 < end; c0 += CHUNK) {
        int cnt = min(end - c0, CHUNK);
        __syncwarp();
        for (int j = (lane >> 2); j < cnt; j += 8) {
            int s = g_csr_src[c0 + j];
            if (hh == 0) sh_s[w8][j] = s;
            float e = g_el[s * 4 + hh];
            float w = __expf(leaky(e + er_hh));
            sh_w[w8][j * 4 + hh] = w;
            swl += w;
        }
        __syncwarp();
#pragma unroll 4
        for (int j = 0; j < cnt; j++) {
            int s = sh_s[w8][j];
            float w = sh_w[w8][j * 4 + h];
            float4 f = feat4[(size_t)s * 32 + lane];
            acc.x = fmaf(f.x, w, acc.x);
            acc.y = fmaf(f.y, w, acc.y);
            acc.z = fmaf(f.z, w, acc.z);
            acc.w = fmaf(f.w, w, acc.w);
        }
    }
#pragma unroll
    for (int o = 4; o < 32; o <<= 1) swl += __shfl_xor_sync(0xffffffffu, swl, o);
    float sw = __shfl_sync(0xffffffffu, swl, h);

    float inv = (end > beg) ? (1.0f / sw) : 0.f;
    float4 bv = ((const float4*)bias)[lane];
    float4 o;
    o.x = fmaxf(acc.x * inv + bv.x, 0.f);
    o.y = fmaxf(acc.y * inv + bv.y, 0.f);
    o.z = fmaxf(acc.z * inv + bv.z, 0.f);
    o.w = fmaxf(acc.w * inv + bv.w, 0.f);
    ((float4*)out)[(size_t)warp * 32 + lane] = o;
}

// ---------------- aggregation H=1, D=40 (layer 2) ----------------
__global__ __launch_bounds__(256) void k_agg1(const float* __restrict__ feat,
                                              const float* __restrict__ bias,
                                              float* __restrict__ out, int n) {
    __shared__ int   sh_s[8][CHUNK];
    __shared__ float sh_w[8][CHUNK];
    int warp = (blockIdx.x * blockDim.x + threadIdx.x) >> 5;
    int lane = threadIdx.x & 31;
    int w8 = (threadIdx.x >> 5);
    if (warp >= n) return;
    int beg = g_off[warp], end = g_off[warp + 1];
    float ern = g_er[warp];

    float acc0 = 0.f, acc1 = 0.f, swl = 0.f;
    for (int c0 = beg; c0 < end; c0 += CHUNK) {
        int cnt = min(end - c0, CHUNK);
        __syncwarp();
        for (int j = lane; j < cnt; j += 32) {
            int s = g_csr_src[c0 + j];
            sh_s[w8][j] = s;
            float w = __expf(leaky(g_el[s] + ern));
            sh_w[w8][j] = w;
            swl += w;
        }
        __syncwarp();
#pragma unroll 4
        for (int j = 0; j < cnt; j++) {
            int s = sh_s[w8][j];
            float w = sh_w[w8][j];
            const float* fs = feat + (size_t)s * 40;
            acc0 = fmaf(fs[lane], w, acc0);
            if (lane < 8) acc1 = fmaf(fs[32 + lane], w, acc1);
        }
    }
#pragma unroll
    for (int o = 16; o > 0; o >>= 1) swl += __shfl_xor_sync(0xffffffffu, swl, o);
    float inv = (end > beg) ? (1.0f / swl) : 0.f;
    out[(size_t)warp * 40 + lane] = acc0 * inv + bias[lane];
    if (lane < 8) out[(size_t)warp * 40 + 32 + lane] = acc1 * inv + bias[32 + lane];
}

// ---------------- launch ----------------
extern "C" void kernel_launch(void* const* d_in, const int* in_sizes, int n_in,
                              void* d_out, int out_size) {
    const float* x   = (const float*)d_in[0];
    const int*   src = (const int*)d_in[1];
    const int*   dst = (const int*)d_in[2];
    const float* W0  = (const float*)d_in[3];
    const float* al0 = (const float*)d_in[4];
    const float* ar0 = (const float*)d_in[5];
    const float* b0  = (const float*)d_in[6];
    const float* W1  = (const float*)d_in[7];
    const float* al1 = (const float*)d_in[8];
    const float* ar1 = (const float*)d_in[9];
    const float* b1  = (const float*)d_in[10];
    const float* W2  = (const float*)d_in[11];
    const float* al2 = (const float*)d_in[12];
    const float* ar2 = (const float*)d_in[13];
    const float* b2  = (const float*)d_in[14];

    int n = in_sizes[0] / 256;
    int E = in_sizes[1];
    float* out = (float*)d_out;

    float *feat, *x1, *x2;
    cudaGetSymbolAddress((void**)&feat, g_feat);
    cudaGetSymbolAddress((void**)&x1, g_x1);
    cudaGetSymbolAddress((void**)&x2, g_x2);

    int nb = (n + 1023) / 1024;

    k_zero_cnt<<<(n + 255) / 256, 256>>>(n);
    k_count<<<(E + 255) / 256, 256>>>(dst, E);
    k_scan1<<<nb, 1024>>>(n);
    // launch 4: layer-0 GEMM (ncu window)
    k_gemm_tc<256><<<(n + 127) / 128, 512>>>(x, W0, feat, n);
    k_scan2<<<1, 32>>>(nb);
    k_scan3<<<(n + 255) / 256, 256>>>(n, E);
    k_scatter<<<(E + 255) / 256, 256>>>(src, dst, E);

    // layer 0
    k_eler4<<<(n + 7) / 8, 256>>>(feat, al0, ar0, n);
    k_agg4<<<(n + 7) / 8, 256>>>(feat, b0, x1, n);

    // layer 1
    k_gemm_tc<128><<<(n + 127) / 128, 512>>>(x1, W1, feat, n);
    k_eler4<<<(n + 7) / 8, 256>>>(feat, al1, ar1, n);
    k_agg4<<<(n + 7) / 8, 256>>>(feat, b1, x2, n);

    // layer 2
    k_gemm<128, 40><<<(n + 15) / 16, 128>>>(x2, W2, feat, n);
    k_eler1<<<(n + 7) / 8, 256>>>(feat, al2, ar2, n);
    k_agg1<<<(n + 7) / 8, 256>>>(feat, b2, out, n);
}